// round 15
// baseline (speedup 1.0000x reference)
#include <cuda_runtime.h>
#include <cuda_fp16.h>
#include <cstdint>

constexpr int B = 1024, F = 784, D = 512;
constexpr int TB = 64, TD = 64, TF = 56;     // 784 = 14 * 56
constexpr int SXH = 72;                       // smem stride in halfs (144B)
constexpr int NSTEP = F / TF;                 // 14
constexpr int KH = NSTEP / 2;                 // 7 per cluster rank
constexpr int CHUNKS = TF * 2 / 16;           // 7 x 16B chunks per row
constexpr int NST = 3;                        // pipeline stages

// fp16 pre-converted operands
__device__ __half g_xh[B * F];
__device__ __half g_ch[D * F];   // (Wmin+Wmax)/2
__device__ __half g_rh[D * F];   // (Wmax-Wmin)/2

union U4H { uint4 u; __half2 h[4]; };

__device__ __forceinline__ unsigned h2u(__half2 v) {
    union { __half2 h; unsigned u; } c; c.h = v; return c.u;
}
__device__ __forceinline__ __half2 u2h(unsigned v) {
    union { __half2 h; unsigned u; } c; c.u = v; return c.h;
}
__device__ __forceinline__ unsigned smem_u32(const void* p) {
    unsigned a;
    asm("{ .reg .u64 t; cvta.to.shared.u64 t, %1; cvt.u32.u64 %0, t; }" : "=r"(a) : "l"(p));
    return a;
}
__device__ __forceinline__ void st_peer_u32(unsigned local_addr, unsigned val, unsigned rank) {
    asm volatile(
        "{ .reg .b32 r; mapa.shared::cluster.u32 r, %0, %2; "
        "st.shared::cluster.u32 [r], %1; }"
        :: "r"(local_addr), "r"(val), "r"(rank) : "memory");
}
__device__ __forceinline__ void cp16(unsigned smem_dst, const void* gsrc) {
    asm volatile("cp.async.ca.shared.global [%0], [%1], 16;"
                 :: "r"(smem_dst), "l"(gsrc) : "memory");
}
__device__ __forceinline__ void cp_commit() { asm volatile("cp.async.commit_group;" ::: "memory"); }
__device__ __forceinline__ void cp_wait1()  { asm volatile("cp.async.wait_group 1;" ::: "memory"); }

// ---- prep: fp32 -> fp16 transform, one launch ----
__global__ __launch_bounds__(256)
void prep_kernel(const float* __restrict__ x,
                 const float* __restrict__ wmin,
                 const float* __restrict__ wmax)
{
    int bx = blockIdx.x;
    if (bx < 392) {
        int i = (bx * 256 + threadIdx.x) * 8;
        float4 a = *(const float4*)&x[i];
        float4 b = *(const float4*)&x[i + 4];
        uint4 o;
        o.x = h2u(__floats2half2_rn(a.x, a.y));
        o.y = h2u(__floats2half2_rn(a.z, a.w));
        o.z = h2u(__floats2half2_rn(b.x, b.y));
        o.w = h2u(__floats2half2_rn(b.z, b.w));
        *(uint4*)&g_xh[i] = o;
    } else {
        int i = ((bx - 392) * 256 + threadIdx.x) * 8;
        float4 n0 = *(const float4*)&wmin[i];
        float4 n1 = *(const float4*)&wmin[i + 4];
        float4 m0 = *(const float4*)&wmax[i];
        float4 m1 = *(const float4*)&wmax[i + 4];
        uint4 oc, orr;
        oc.x  = h2u(__floats2half2_rn(0.5f*(n0.x+m0.x), 0.5f*(n0.y+m0.y)));
        oc.y  = h2u(__floats2half2_rn(0.5f*(n0.z+m0.z), 0.5f*(n0.w+m0.w)));
        oc.z  = h2u(__floats2half2_rn(0.5f*(n1.x+m1.x), 0.5f*(n1.y+m1.y)));
        oc.w  = h2u(__floats2half2_rn(0.5f*(n1.z+m1.z), 0.5f*(n1.w+m1.w)));
        orr.x = h2u(__floats2half2_rn(0.5f*(m0.x-n0.x), 0.5f*(m0.y-n0.y)));
        orr.y = h2u(__floats2half2_rn(0.5f*(m0.z-n0.z), 0.5f*(m0.w-n0.w)));
        orr.z = h2u(__floats2half2_rn(0.5f*(m1.x-n1.x), 0.5f*(m1.y-n1.y)));
        orr.w = h2u(__floats2half2_rn(0.5f*(m1.z-n1.z), 0.5f*(m1.w-n1.w)));
        *(uint4*)&g_ch[i] = oc;
        *(uint4*)&g_rh[i] = orr;
    }
}

__global__ __launch_bounds__(256, 2) __cluster_dims__(1, 1, 2)
void dendral_kernel(float* __restrict__ out)
{
    // 3-stage pipelined fp16 tiles (cp.async targets). 83 KB total.
    __shared__ __half sx[NST][TB * SXH];   // reused as mailbox AFTER cluster barrier
    __shared__ __half sc[NST][TD * SXH];
    __shared__ __half sr[NST][TD * SXH];

    const int tid = threadIdx.x;
    const int tx  = tid & 7;      // d lane (8 wide -> conflict-free W LDS)
    const int ty  = tid >> 3;     // b lane (32 wide)
    const int d0  = blockIdx.x * TD;
    const int b0  = blockIdx.y * TB;
    const int zh  = blockIdx.z;   // cluster rank
    const int k0  = zh * KH;

    const unsigned sx_base = smem_u32(sx);
    const unsigned sc_base = smem_u32(sc);
    const unsigned sr_base = smem_u32(sr);
    const unsigned STGB = (unsigned)(TB * SXH * 2);   // bytes per stage

    auto prefetch = [&](int s, int k, bool live) {
        if (live) {
            const int f0h = k * TF;
            #pragma unroll
            for (int t = 0; t < 2; ++t) {
                int it = tid + t * 256;
                if (it < TB * CHUNKS) {       // 448 chunks per array
                    int row = it / CHUNKS;
                    int ch  = it % CHUNKS;
                    unsigned so = (unsigned)s * STGB + (unsigned)(row * SXH + ch * 8) * 2u;
                    cp16(sx_base + so, &g_xh[(b0 + row) * F + f0h + ch * 8]);
                    cp16(sc_base + so, &g_ch[(d0 + row) * F + f0h + ch * 8]);
                    cp16(sr_base + so, &g_rh[(d0 + row) * F + f0h + ch * 8]);
                }
            }
        }
        cp_commit();
    };

    const __half2 INF2 = __halves2half2(__ushort_as_half(0x7C00), __ushort_as_half(0x7C00));
    __half2 acc[8][2];           // 8 d-frags (tx + 8i), 2 b-frags (ty + 32j)
    #pragma unroll
    for (int i = 0; i < 8; ++i)
        #pragma unroll
        for (int j = 0; j < 2; ++j) acc[i][j] = INF2;

    // Prologue: two stages in flight.
    prefetch(0, k0, true);
    prefetch(1, k0 + 1, true);

    for (int kk = 0; kk < KH; ++kk) {
        const int cur = kk % NST;

        cp_wait1();        // group carrying stage `cur` retired
        __syncthreads();   // publish stage cur; retire compute on stage (cur+2)%3

        prefetch((kk + 2) % NST, k0 + kk + 2, kk + 2 < KH);

        #pragma unroll
        for (int f = 0; f < TF; f += 8) {
            U4H xv[2];
            #pragma unroll
            for (int j = 0; j < 2; ++j)
                xv[j].u = *(const uint4*)&sx[cur][(ty + 32 * j) * SXH + f];

            #pragma unroll
            for (int i = 0; i < 8; ++i) {
                U4H cv, rv;
                cv.u = *(const uint4*)&sc[cur][(tx + 8 * i) * SXH + f];
                rv.u = *(const uint4*)&sr[cur][(tx + 8 * i) * SXH + f];
                #pragma unroll
                for (int j = 0; j < 2; ++j) {
                    // m = r - |x - c| == min(x - Wmin, Wmax - x)
                    __half2 m0 = __hsub2(rv.h[0], __habs2(__hsub2(xv[j].h[0], cv.h[0])));
                    __half2 m1 = __hsub2(rv.h[1], __habs2(__hsub2(xv[j].h[1], cv.h[1])));
                    __half2 m2 = __hsub2(rv.h[2], __habs2(__hsub2(xv[j].h[2], cv.h[2])));
                    __half2 m3 = __hsub2(rv.h[3], __habs2(__hsub2(xv[j].h[3], cv.h[3])));
                    __half2 t01 = __hmin2(m0, m1);
                    __half2 t23 = __hmin2(m2, m3);
                    acc[i][j] = __hmin2(acc[i][j], __hmin2(t01, t23));
                }
            }
        }
    }

    // ---- cross-rank reduction over DSMEM (mailbox aliases sx) ----
    __syncthreads();   // this CTA's compute done

    // Cluster rendezvous BEFORE rank 1 writes rank 0's sx (R13 race fix).
    asm volatile("barrier.cluster.arrive.aligned;" ::: "memory");
    asm volatile("barrier.cluster.wait.aligned;"   ::: "memory");

    unsigned* sred = (unsigned*)&sx[0][0];
    const unsigned sred_base = smem_u32(sred);

    if (zh == 1) {
        #pragma unroll
        for (int i = 0; i < 8; ++i)
            #pragma unroll
            for (int j = 0; j < 2; ++j)
                st_peer_u32(sred_base + (unsigned)(tid * 16 + i * 2 + j) * 4u,
                            h2u(acc[i][j]), 0u);
    }
    asm volatile("barrier.cluster.arrive.aligned;" ::: "memory");
    asm volatile("barrier.cluster.wait.aligned;"   ::: "memory");

    if (zh == 0) {
        #pragma unroll
        for (int i = 0; i < 8; ++i)
            #pragma unroll
            for (int j = 0; j < 2; ++j) {
                __half2 p = u2h(sred[tid * 16 + i * 2 + j]);
                __half2 m = __hmin2(acc[i][j], p);
                float lo = __low2float(m);
                float hi = __high2float(m);
                int b = b0 + ty + 32 * j;
                int d = d0 + tx + 8 * i;
                out[b * D + d] = fminf(lo, hi);
            }
    }
}

extern "C" void kernel_launch(void* const* d_in, const int* in_sizes, int n_in,
                              void* d_out, int out_size)
{
    const float* x    = (const float*)d_in[0];
    const float* wmin = (const float*)d_in[1];
    const float* wmax = (const float*)d_in[2];
    float* out = (float*)d_out;

    prep_kernel<<<588, 256>>>(x, wmin, wmax);

    dim3 grid(D / TD, B / TB, 2);   // (8, 16, 2) = 256 CTAs, 128 clusters
    dendral_kernel<<<grid, 256>>>(out);
}

// round 16
// speedup vs baseline: 1.0450x; 1.0450x over previous
#include <cuda_runtime.h>
#include <cuda_fp16.h>
#include <cstdint>

constexpr int B = 1024, F = 784, D = 512;
constexpr int TB = 64, TD = 64, TF = 56;     // 784 = 14 * 56
constexpr int SXH = 72;                       // smem stride in halfs (144B)
constexpr int NSTEP = F / TF;                 // 14
constexpr int KH = NSTEP / 2;                 // 7 per cluster rank
constexpr int CHUNKS = TF * 2 / 16;           // 7 x 16B chunks per row
constexpr int NST = 3;                        // pipeline stages

// fp16 pre-converted operands
__device__ __half g_xh[B * F];
__device__ __half g_ch[D * F];   // (Wmin+Wmax)/2
__device__ __half g_rh[D * F];   // (Wmax-Wmin)/2

union U4H { uint4 u; __half2 h[4]; };

__device__ __forceinline__ unsigned h2u(__half2 v) {
    union { __half2 h; unsigned u; } c; c.h = v; return c.u;
}
__device__ __forceinline__ __half2 u2h(unsigned v) {
    union { __half2 h; unsigned u; } c; c.u = v; return c.h;
}
__device__ __forceinline__ unsigned smem_u32(const void* p) {
    unsigned a;
    asm("{ .reg .u64 t; cvta.to.shared.u64 t, %1; cvt.u32.u64 %0, t; }" : "=r"(a) : "l"(p));
    return a;
}
__device__ __forceinline__ void st_peer_u32(unsigned local_addr, unsigned val, unsigned rank) {
    asm volatile(
        "{ .reg .b32 r; mapa.shared::cluster.u32 r, %0, %2; "
        "st.shared::cluster.u32 [r], %1; }"
        :: "r"(local_addr), "r"(val), "r"(rank) : "memory");
}
__device__ __forceinline__ void cp16(unsigned smem_dst, const void* gsrc) {
    asm volatile("cp.async.ca.shared.global [%0], [%1], 16;"
                 :: "r"(smem_dst), "l"(gsrc) : "memory");
}
__device__ __forceinline__ void cp_commit() { asm volatile("cp.async.commit_group;" ::: "memory"); }
__device__ __forceinline__ void cp_wait1()  { asm volatile("cp.async.wait_group 1;" ::: "memory"); }

// ---- prep: fp32 -> fp16 transform. 4 elems/thread, 1176 CTAs (high MLP). ----
__global__ __launch_bounds__(256)
void prep_kernel(const float* __restrict__ x,
                 const float* __restrict__ wmin,
                 const float* __restrict__ wmax)
{
    int bx = blockIdx.x;
    if (bx < 784) {                         // x: 802816 / (256*4) = 784 CTAs
        int i = (bx * 256 + threadIdx.x) * 4;
        float4 a = *(const float4*)&x[i];
        uint2 o;
        o.x = h2u(__floats2half2_rn(a.x, a.y));
        o.y = h2u(__floats2half2_rn(a.z, a.w));
        *(uint2*)&g_xh[i] = o;
    } else {                                // W: 401408 / (256*4) = 392 CTAs
        int i = ((bx - 784) * 256 + threadIdx.x) * 4;
        float4 n = *(const float4*)&wmin[i];
        float4 m = *(const float4*)&wmax[i];
        uint2 oc, orr;
        oc.x  = h2u(__floats2half2_rn(0.5f*(n.x+m.x), 0.5f*(n.y+m.y)));
        oc.y  = h2u(__floats2half2_rn(0.5f*(n.z+m.z), 0.5f*(n.w+m.w)));
        orr.x = h2u(__floats2half2_rn(0.5f*(m.x-n.x), 0.5f*(m.y-n.y)));
        orr.y = h2u(__floats2half2_rn(0.5f*(m.z-n.z), 0.5f*(m.w-n.w)));
        *(uint2*)&g_ch[i] = oc;
        *(uint2*)&g_rh[i] = orr;
    }
}

__global__ __launch_bounds__(256, 2) __cluster_dims__(1, 1, 2)
void dendral_kernel(float* __restrict__ out)
{
    // 3-stage pipelined fp16 tiles (cp.async targets). 83 KB total.
    __shared__ __half sx[NST][TB * SXH];   // reused as mailbox AFTER cluster barrier
    __shared__ __half sc[NST][TD * SXH];
    __shared__ __half sr[NST][TD * SXH];

    const int tid = threadIdx.x;
    const int tx  = tid & 15;     // d lane
    const int ty  = tid >> 4;     // b lane
    const int d0  = blockIdx.x * TD;
    const int b0  = blockIdx.y * TB;
    const int zh  = blockIdx.z;   // cluster rank
    const int k0  = zh * KH;

    const unsigned sx_base = smem_u32(sx);
    const unsigned sc_base = smem_u32(sc);
    const unsigned sr_base = smem_u32(sr);
    const unsigned STGB = (unsigned)(TB * SXH * 2);   // bytes per stage

    auto prefetch = [&](int s, int k, bool live) {
        if (live) {
            const int f0h = k * TF;
            #pragma unroll
            for (int t = 0; t < 2; ++t) {
                int it = tid + t * 256;
                if (it < TB * CHUNKS) {       // 448 chunks per array
                    int row = it / CHUNKS;
                    int ch  = it % CHUNKS;
                    unsigned so = (unsigned)s * STGB + (unsigned)(row * SXH + ch * 8) * 2u;
                    cp16(sx_base + so, &g_xh[(b0 + row) * F + f0h + ch * 8]);
                    cp16(sc_base + so, &g_ch[(d0 + row) * F + f0h + ch * 8]);
                    cp16(sr_base + so, &g_rh[(d0 + row) * F + f0h + ch * 8]);
                }
            }
        }
        cp_commit();
    };

    const __half2 INF2 = __halves2half2(__ushort_as_half(0x7C00), __ushort_as_half(0x7C00));
    // Two independent accumulator banks per (i,j): shorter dep chains, same op count.
    __half2 accA[4][4], accB[4][4];
    #pragma unroll
    for (int i = 0; i < 4; ++i)
        #pragma unroll
        for (int j = 0; j < 4; ++j) { accA[i][j] = INF2; accB[i][j] = INF2; }

    // Prologue: two stages in flight.
    prefetch(0, k0, true);
    prefetch(1, k0 + 1, true);

    for (int kk = 0; kk < KH; ++kk) {
        const int cur = kk % NST;

        cp_wait1();        // group carrying stage `cur` retired
        __syncthreads();   // publish stage cur; retire compute on stage (cur+2)%3

        prefetch((kk + 2) % NST, k0 + kk + 2, kk + 2 < KH);

        #pragma unroll
        for (int f = 0; f < TF; f += 8) {
            U4H xv[4];
            #pragma unroll
            for (int j = 0; j < 4; ++j)
                xv[j].u = *(const uint4*)&sx[cur][(ty + 16 * j) * SXH + f];

            #pragma unroll
            for (int i = 0; i < 4; ++i) {
                U4H cv, rv;
                cv.u = *(const uint4*)&sc[cur][(tx + 16 * i) * SXH + f];
                rv.u = *(const uint4*)&sr[cur][(tx + 16 * i) * SXH + f];
                #pragma unroll
                for (int j = 0; j < 4; ++j) {
                    // m = r - |x - c| == min(x - Wmin, Wmax - x)
                    __half2 m0 = __hsub2(rv.h[0], __habs2(__hsub2(xv[j].h[0], cv.h[0])));
                    __half2 m1 = __hsub2(rv.h[1], __habs2(__hsub2(xv[j].h[1], cv.h[1])));
                    __half2 m2 = __hsub2(rv.h[2], __habs2(__hsub2(xv[j].h[2], cv.h[2])));
                    __half2 m3 = __hsub2(rv.h[3], __habs2(__hsub2(xv[j].h[3], cv.h[3])));
                    accA[i][j] = __hmin2(accA[i][j], __hmin2(m0, m1));
                    accB[i][j] = __hmin2(accB[i][j], __hmin2(m2, m3));
                }
            }
        }
    }

    // Merge the two banks.
    __half2 acc[4][4];
    #pragma unroll
    for (int i = 0; i < 4; ++i)
        #pragma unroll
        for (int j = 0; j < 4; ++j) acc[i][j] = __hmin2(accA[i][j], accB[i][j]);

    // ---- cross-rank reduction over DSMEM (mailbox aliases sx) ----
    __syncthreads();   // this CTA's compute done

    // Cluster rendezvous BEFORE rank 1 writes rank 0's sx (R13 race fix).
    asm volatile("barrier.cluster.arrive.aligned;" ::: "memory");
    asm volatile("barrier.cluster.wait.aligned;"   ::: "memory");

    unsigned* sred = (unsigned*)&sx[0][0];
    const unsigned sred_base = smem_u32(sred);

    if (zh == 1) {
        #pragma unroll
        for (int i = 0; i < 4; ++i)
            #pragma unroll
            for (int j = 0; j < 4; ++j)
                st_peer_u32(sred_base + (unsigned)(tid * 16 + i * 4 + j) * 4u,
                            h2u(acc[i][j]), 0u);
    }
    asm volatile("barrier.cluster.arrive.aligned;" ::: "memory");
    asm volatile("barrier.cluster.wait.aligned;"   ::: "memory");

    if (zh == 0) {
        #pragma unroll
        for (int i = 0; i < 4; ++i)
            #pragma unroll
            for (int j = 0; j < 4; ++j) {
                __half2 p = u2h(sred[tid * 16 + i * 4 + j]);
                __half2 m = __hmin2(acc[i][j], p);
                float lo = __low2float(m);
                float hi = __high2float(m);
                int b = b0 + ty + 16 * j;
                int d = d0 + tx + 16 * i;
                out[b * D + d] = fminf(lo, hi);
            }
    }
}

extern "C" void kernel_launch(void* const* d_in, const int* in_sizes, int n_in,
                              void* d_out, int out_size)
{
    const float* x    = (const float*)d_in[0];
    const float* wmin = (const float*)d_in[1];
    const float* wmax = (const float*)d_in[2];
    float* out = (float*)d_out;

    prep_kernel<<<1176, 256>>>(x, wmin, wmax);

    dim3 grid(D / TD, B / TB, 2);   // (8, 16, 2) = 256 CTAs, 128 clusters
    dendral_kernel<<<grid, 256>>>(out);
}